// round 14
// baseline (speedup 1.0000x reference)
#include <cuda_runtime.h>
#include <cuda_fp16.h>
#include <math.h>
#include <stdint.h>

#define D 128
#define MAXN 50000
#define MAXE 1000000
#define SZF (50000L * 128L)

__device__ float g_buf[22L * SZF + 2 * 131072 + 4 * 32768 + 1024];
__device__ int g_deg[2 * MAXN];
__device__ int g_idx[2 * MAXE + 2 * (MAXN + 8) + 2 * MAXN];

// ---------------- helpers ----------------
__device__ __forceinline__ uint32_t s2u(const void* p) {
    uint32_t a;
    asm("{ .reg .u64 t; cvta.to.shared.u64 t, %1; cvt.u32.u64 %0, t; }" : "=r"(a) : "l"(p));
    return a;
}
__device__ __host__ __forceinline__ uint32_t SWZ(uint32_t x) { return x ^ ((x >> 3) & 0x70); }

__device__ __forceinline__ float sigf(float x) { return 1.f / (1.f + expf(-x)); }

__device__ __forceinline__ uint2 pack4_hi(float4 v) {
    __half2 a = __floats2half2_rn(v.x, v.y);
    __half2 b = __floats2half2_rn(v.z, v.w);
    uint2 r;
    r.x = *reinterpret_cast<uint32_t*>(&a);
    r.y = *reinterpret_cast<uint32_t*>(&b);
    return r;
}

__device__ __forceinline__ void acc_u2(float4& s, uint2 v) {
    float2 p0 = __half22float2(*reinterpret_cast<__half2*>(&v.x));
    float2 p1 = __half22float2(*reinterpret_cast<__half2*>(&v.y));
    s.x += p0.x; s.y += p0.y; s.z += p1.x; s.w += p1.y;
}

// ---------------- sort-by-destination ----------------
__global__ void zero_int(int* p, int n) {
    int i = blockIdx.x * blockDim.x + threadIdx.x;
    if (i < n) p[i] = 0;
}

__global__ void count_deg(const int* __restrict__ dst, int E, int* __restrict__ deg) {
    int i = blockIdx.x * blockDim.x + threadIdx.x;
    if (i < E) atomicAdd(&deg[dst[i]], 1);
}

__global__ void scan_kernel(const int* __restrict__ deg, int n,
                            int* __restrict__ off, int* __restrict__ cur) {
    __shared__ int wsum[32];
    __shared__ int carry;
    int tid = threadIdx.x, lane = tid & 31, w = tid >> 5;
    if (tid == 0) { carry = 0; off[0] = 0; }
    __syncthreads();
    for (int base = 0; base < n; base += 1024) {
        int i = base + tid;
        int v = (i < n) ? deg[i] : 0;
        int x = v;
#pragma unroll
        for (int o = 1; o < 32; o <<= 1) {
            int y = __shfl_up_sync(0xFFFFFFFFu, x, o);
            if (lane >= o) x += y;
        }
        if (lane == 31) wsum[w] = x;
        __syncthreads();
        if (w == 0) {
            int s = wsum[lane];
#pragma unroll
            for (int o = 1; o < 32; o <<= 1) {
                int y = __shfl_up_sync(0xFFFFFFFFu, s, o);
                if (lane >= o) s += y;
            }
            wsum[lane] = s;
        }
        __syncthreads();
        int incl = x + (w ? wsum[w - 1] : 0) + carry;
        if (i < n) { off[i + 1] = incl; cur[i] = incl - v; }
        __syncthreads();
        if (tid == 1023) carry = incl;
        __syncthreads();
    }
}

__global__ void scatter_kernel(const int* __restrict__ src, const int* __restrict__ dst,
                               int E, int* __restrict__ cur, int* __restrict__ ssrc) {
    int i = blockIdx.x * blockDim.x + threadIdx.x;
    if (i < E) {
        int pos = atomicAdd(&cur[dst[i]], 1);
        ssrc[pos] = src[i];
    }
}

// ---------------- packing ----------------
__global__ void pack_hi(const float* __restrict__ src, int M, char* __restrict__ dst) {
    long i = blockIdx.x * (long)blockDim.x + threadIdx.x;
    if (i >= (long)M * 32) return;
    int row = (int)(i >> 5);
    int c4 = ((int)i & 31) * 4;
    float4 v = ((const float4*)src)[i];
    uint2 hu = pack4_hi(v);
    int q = c4 >> 6;
    int inner = c4 & 63;
    uint32_t sw = SWZ((uint32_t)row * 128u + (uint32_t)inner * 2u);
    long Mb = (long)M * 128;
    *(uint2*)(dst + (long)q * Mb + sw) = hu;
}

// pull aggregation from fp32 tables (no pack dependency), warp-per-node
__global__ void gather2_f(const float* __restrict__ fx, const float* __restrict__ fh,
                          const int* __restrict__ off, const int* __restrict__ ssrc, int n,
                          char* __restrict__ Ox, char* __restrict__ Oh, long MbD) {
    long gid = blockIdx.x * (long)blockDim.x + threadIdx.x;
    int node = (int)(gid >> 5), lane = (int)(gid & 31);
    if (node >= n) return;
    int s0 = off[node], s1 = off[node + 1];
    int c4 = lane * 4;
    float4 sx = make_float4(0.f, 0.f, 0.f, 0.f);
    float4 sh = make_float4(0.f, 0.f, 0.f, 0.f);
    int i = s0;
    for (; i + 1 < s1; i += 2) {
        int a = ssrc[i], b = ssrc[i + 1];
        float4 xa = *(const float4*)(fx + (long)a * D + c4);
        float4 xb = *(const float4*)(fx + (long)b * D + c4);
        float4 ha = *(const float4*)(fh + (long)a * D + c4);
        float4 hb = *(const float4*)(fh + (long)b * D + c4);
        sx.x += xa.x + xb.x; sx.y += xa.y + xb.y; sx.z += xa.z + xb.z; sx.w += xa.w + xb.w;
        sh.x += ha.x + hb.x; sh.y += ha.y + hb.y; sh.z += ha.z + hb.z; sh.w += ha.w + hb.w;
    }
    if (i < s1) {
        int a = ssrc[i];
        float4 xa = *(const float4*)(fx + (long)a * D + c4);
        float4 ha = *(const float4*)(fh + (long)a * D + c4);
        sx.x += xa.x; sx.y += xa.y; sx.z += xa.z; sx.w += xa.w;
        sh.x += ha.x; sh.y += ha.y; sh.z += ha.z; sh.w += ha.w;
    }
    float inv = 1.f / (float)max(s1 - s0, 1);
    sx.x *= inv; sx.y *= inv; sx.z *= inv; sx.w *= inv;
    sh.x *= inv; sh.y *= inv; sh.z *= inv; sh.w *= inv;
    int q = c4 >> 6;
    int inner = c4 & 63;
    uint32_t swd = SWZ((uint32_t)node * 128u + (uint32_t)inner * 2u);
    *(uint2*)(Ox + (long)q * MbD + swd) = pack4_hi(sx);
    *(uint2*)(Oh + (long)q * MbD + swd) = pack4_hi(sh);
}

// pull aggregation of a packed fp16 table -> packed output
__global__ void gather1_p(const char* __restrict__ P, long MbS,
                          const int* __restrict__ off, const int* __restrict__ ssrc, int n,
                          char* __restrict__ dstP, long MbD) {
    long gid = blockIdx.x * (long)blockDim.x + threadIdx.x;
    int node = (int)(gid >> 5), lane = (int)(gid & 31);
    if (node >= n) return;
    int s0 = off[node], s1 = off[node + 1];
    int c4 = lane * 4;
    int q = c4 >> 6;
    int inner = c4 & 63;
    long qb = (long)q * MbS;
    float4 acc = make_float4(0.f, 0.f, 0.f, 0.f);
    int i = s0;
    for (; i + 3 < s1; i += 4) {
        int a0 = ssrc[i], a1 = ssrc[i + 1], a2 = ssrc[i + 2], a3 = ssrc[i + 3];
        uint2 v0 = *(const uint2*)(P + qb + SWZ((uint32_t)a0 * 128u + (uint32_t)inner * 2u));
        uint2 v1 = *(const uint2*)(P + qb + SWZ((uint32_t)a1 * 128u + (uint32_t)inner * 2u));
        uint2 v2 = *(const uint2*)(P + qb + SWZ((uint32_t)a2 * 128u + (uint32_t)inner * 2u));
        uint2 v3 = *(const uint2*)(P + qb + SWZ((uint32_t)a3 * 128u + (uint32_t)inner * 2u));
        acc_u2(acc, v0); acc_u2(acc, v1); acc_u2(acc, v2); acc_u2(acc, v3);
    }
    for (; i < s1; i++) {
        int a = ssrc[i];
        acc_u2(acc, *(const uint2*)(P + qb + SWZ((uint32_t)a * 128u + (uint32_t)inner * 2u)));
    }
    float inv = 1.f / (float)max(s1 - s0, 1);
    acc.x *= inv; acc.y *= inv; acc.z *= inv; acc.w *= inv;
    uint32_t swd = SWZ((uint32_t)node * 128u + (uint32_t)inner * 2u);
    *(uint2*)(dstP + (long)q * MbD + swd) = pack4_hi(acc);
}

// ---------------- weight packing (fp16) ----------------
__global__ void pack_w_zr(const float* __restrict__ Wl, const float* __restrict__ Wr,
                          char* __restrict__ dst, int t) {
    int j = blockIdx.x * blockDim.x + threadIdx.x;
    if (j >= 4 * 256 * 128) return;
    int k = j & 127;
    int n = (j >> 7) & 255;
    int p = j >> 15;
    int gz = (n < 128) ? 0 : 2;
    int cc = n & 127;
    int g = gz + (p >> 1);
    const float* S = (p & 1) ? Wr : Wl;
    float w = S[((long)(g * 2 + t) * 128 + k) * 128 + cc];
    __half h = __float2half_rn(w);
    int q = k >> 6;
    int inner = k & 63;
    uint32_t sw = SWZ((uint32_t)n * 128u + (uint32_t)inner * 2u);
    const int Nb = 256 * 128;
    *(unsigned short*)(dst + (size_t)(p * 2 + q) * Nb + sw) = *reinterpret_cast<unsigned short*>(&h);
}

__global__ void pack_w2(const float* __restrict__ Wl, const float* __restrict__ Wr,
                        char* __restrict__ dst, int g, int t, int pbase) {
    int j = blockIdx.x * blockDim.x + threadIdx.x;
    if (j >= 2 * 128 * 128) return;
    int k = j & 127;
    int n = (j >> 7) & 127;
    int p = j >> 14;
    const float* S = p ? Wr : Wl;
    float w = S[((long)(g * 2 + t) * 128 + k) * 128 + n];
    __half h = __float2half_rn(w);
    int q = k >> 6;
    int inner = k & 63;
    uint32_t sw = SWZ((uint32_t)n * 128u + (uint32_t)inner * 2u);
    const int Nb = 128 * 128;
    *(unsigned short*)(dst + (size_t)((pbase + p) * 2 + q) * Nb + sw) = *reinterpret_cast<unsigned short*>(&h);
}

__global__ void build_bias(const float* __restrict__ b,
                           float* bzr_n, float* bzr_u, float* bc_n, float* bc_u) {
    int c = threadIdx.x;
    if (c >= 128) return;
#define BB(g, t) b[((g) * 2 + (t)) * 128 + c]
    bzr_n[c]       = BB(0, 0) + BB(1, 0);
    bzr_n[128 + c] = BB(2, 0) + BB(3, 0);
    bzr_u[c]       = BB(0, 1) + BB(1, 1);
    bzr_u[128 + c] = BB(2, 1) + BB(3, 1);
    bc_n[c] = BB(4, 0) + BB(5, 0);
    bc_u[c] = BB(4, 1) + BB(5, 1);
#undef BB
}

// ---------------- HMMA GEMM (round-10 config: 256 thr, 4x2 warps) ----------
struct GP {
    const char* hi[4];
    const char* B;
    const float* bias;
    const float* H;
    const float* Z;
    float* out0;
    char* outHR;
    long Mb;
    int M, N, nparts, mode;   // mode 0=zr, 2=ch
};

__device__ __forceinline__ void epi_pair(const GP& g, int row, int c, float v0, float v1) {
    v0 += g.bias[c];
    v1 += g.bias[c + 1];
    long rb = (long)row * D;
    if (g.mode == 0) {
        if (c < 128) {
            g.out0[rb + c] = sigf(v0);
            g.out0[rb + c + 1] = sigf(v1);
        } else {
            int cc = c - 128;
            float r0 = sigf(v0) * g.H[rb + cc];
            float r1 = sigf(v1) * g.H[rb + cc + 1];
            __half2 h = __floats2half2_rn(r0, r1);
            uint32_t sw = SWZ((uint32_t)row * 128u + (uint32_t)(cc & 63) * 2u);
            int q = cc >> 6;
            *(uint32_t*)(g.outHR + (long)q * g.Mb + sw) = *reinterpret_cast<uint32_t*>(&h);
        }
    } else {
        float z0 = g.Z[rb + c], z1 = g.Z[rb + c + 1];
        float h0 = g.H[rb + c], h1 = g.H[rb + c + 1];
        float t0 = tanhf(v0);
        float t1 = tanhf(v1);
        g.out0[rb + c] = z0 * h0 + (1.f - z0) * t0;
        g.out0[rb + c + 1] = z1 * h1 + (1.f - z1) * t1;
    }
}

__global__ void __launch_bounds__(256) gemm_mma(GP g) {
    extern __shared__ char smem[];
    uint32_t sb = s2u(smem);
    int tid = threadIdx.x;
    int lane = tid & 31, wid = tid >> 5;
    int wm = wid & 3, wn = wid >> 2;
    int row0 = blockIdx.x * 128;
    int col0 = blockIdx.y * 128;
    long Nb = (long)g.N * 128;
    int C = g.nparts * 2;

    float acc[2][8][4];
#pragma unroll
    for (int i = 0; i < 2; i++)
#pragma unroll
        for (int j = 0; j < 8; j++)
#pragma unroll
            for (int k = 0; k < 4; k++) acc[i][j][k] = 0.f;

    auto issue = [&](int t) {
        int buf = t % 3;
        int p = t >> 1, q = t & 1;
        const char* Asrc = g.hi[p] + (long)q * g.Mb + (long)row0 * 128;
        const char* Bsrc = g.B + (size_t)(p * 2 + q) * Nb + (long)col0 * 128;
        uint32_t Ad = sb + (uint32_t)buf * 32768u;
        uint32_t Bd = Ad + 16384u;
#pragma unroll
        for (int j = 0; j < 4; j++) {
            int idx = tid + j * 256;
            uint32_t sz = (row0 + (idx >> 3) < g.M) ? 16u : 0u;
            asm volatile("cp.async.cg.shared.global [%0], [%1], 16, %2;"
                         :: "r"(Ad + idx * 16), "l"(Asrc + (long)idx * 16), "r"(sz));
        }
#pragma unroll
        for (int j = 0; j < 4; j++) {
            int idx = tid + j * 256;
            asm volatile("cp.async.cg.shared.global [%0], [%1], 16;"
                         :: "r"(Bd + idx * 16), "l"(Bsrc + (long)idx * 16));
        }
        asm volatile("cp.async.commit_group;" ::: "memory");
    };

    issue(0);
    issue(1);
    issue(2);

    for (int t = 0; t < C; t++) {
        int rem = C - t;
        if (rem > 2)       asm volatile("cp.async.wait_group 2;" ::: "memory");
        else if (rem == 2) asm volatile("cp.async.wait_group 1;" ::: "memory");
        else               asm volatile("cp.async.wait_group 0;" ::: "memory");
        __syncthreads();
        uint32_t Ab = sb + (uint32_t)(t % 3) * 32768u;
        uint32_t Bb = Ab + 16384u;
#pragma unroll
        for (int kk = 0; kk < 4; kk++) {
            uint32_t a[2][4];
#pragma unroll
            for (int mi = 0; mi < 2; mi++) {
                int rr = wm * 32 + mi * 16 + (lane & 15);
                int byt = kk * 32 + ((lane >> 4) << 4);
                uint32_t ad = Ab + SWZ((uint32_t)(rr * 128 + byt));
                asm volatile("ldmatrix.sync.aligned.m8n8.x4.shared.b16 {%0,%1,%2,%3}, [%4];"
                    : "=r"(a[mi][0]), "=r"(a[mi][1]), "=r"(a[mi][2]), "=r"(a[mi][3])
                    : "r"(ad));
            }
            uint32_t b[8][2];
#pragma unroll
            for (int nj = 0; nj < 4; nj++) {
                int nn = wn * 64 + nj * 16 + ((lane >> 4) << 3) + (lane & 7);
                int byt = kk * 32 + (((lane >> 3) & 1) << 4);
                uint32_t bd2 = Bb + SWZ((uint32_t)(nn * 128 + byt));
                asm volatile("ldmatrix.sync.aligned.m8n8.x4.shared.b16 {%0,%1,%2,%3}, [%4];"
                    : "=r"(b[nj * 2][0]), "=r"(b[nj * 2][1]),
                      "=r"(b[nj * 2 + 1][0]), "=r"(b[nj * 2 + 1][1])
                    : "r"(bd2));
            }
#pragma unroll
            for (int mi = 0; mi < 2; mi++)
#pragma unroll
                for (int ni = 0; ni < 8; ni++) {
                    asm volatile(
                        "mma.sync.aligned.m16n8k16.row.col.f32.f16.f16.f32 "
                        "{%0,%1,%2,%3}, {%4,%5,%6,%7}, {%8,%9}, {%0,%1,%2,%3};"
                        : "+f"(acc[mi][ni][0]), "+f"(acc[mi][ni][1]),
                          "+f"(acc[mi][ni][2]), "+f"(acc[mi][ni][3])
                        : "r"(a[mi][0]), "r"(a[mi][1]), "r"(a[mi][2]), "r"(a[mi][3]),
                          "r"(b[ni][0]), "r"(b[ni][1]));
                }
        }
        __syncthreads();
        if (t + 3 < C) issue(t + 3);
    }

    int lr = lane >> 2, lc = (lane & 3) * 2;
#pragma unroll
    for (int mi = 0; mi < 2; mi++)
#pragma unroll
        for (int half = 0; half < 2; half++) {
            int row = row0 + wm * 32 + mi * 16 + half * 8 + lr;
            if (row < g.M) {
#pragma unroll
                for (int ni = 0; ni < 8; ni++) {
                    int c = col0 + wn * 64 + ni * 8 + lc;
                    epi_pair(g, row, c, acc[mi][ni][half * 2], acc[mi][ni][half * 2 + 1]);
                }
            }
        }
}

// ---------------------------------------------------------------------------
extern "C" void kernel_launch(void* const* d_in, const int* in_sizes, int n_in,
                              void* d_out, int out_size) {
    const float* x_user = (const float*)d_in[0];
    const float* x_news = (const float*)d_in[1];
    const float* h_user = (const float*)d_in[2];
    const float* h_news = (const float*)d_in[3];
    const float* Wl     = (const float*)d_in[4];
    const float* Wr     = (const float*)d_in[5];
    const float* bb     = (const float*)d_in[6];
    const int* src_un   = (const int*)d_in[7];
    const int* dst_un   = (const int*)d_in[8];
    const int* src_nu   = (const int*)d_in[9];
    const int* dst_nu   = (const int*)d_in[10];

    int NU = in_sizes[0] / D;
    int NN = in_sizes[1] / D;
    int E1 = in_sizes[7];
    int E2 = in_sizes[9];

    float* base = nullptr;
    int* deg = nullptr;
    int* idx = nullptr;
    cudaGetSymbolAddress((void**)&base, g_buf);
    cudaGetSymbolAddress((void**)&deg, g_deg);
    cudaGetSymbolAddress((void**)&idx, g_idx);

    float* Zn = base + 6 * SZF;
    float* Zu = base + 7 * SZF;
    auto packP = [&](int i) -> char* { return (char*)(base + (10L + i) * SZF); };

    float* wf = base + 22 * SZF;
    char* WzrN = (char*)(wf);
    char* WzrU = (char*)(wf + 131072);
    char* WcN  = (char*)(wf + 262144);
    char* WcU  = (char*)(wf + 262144 + 32768);
    float* bzr_n = wf + 262144 + 4 * 32768;
    float* bzr_u = bzr_n + 256;
    float* bc_n  = bzr_u + 256;
    float* bc_u  = bc_n + 128;

    int* deg_n = deg;
    int* deg_u = deg + MAXN;
    int* ssrc1 = idx;
    int* ssrc2 = idx + MAXE;
    int* off_n = idx + 2 * MAXE;
    int* off_u = off_n + (MAXN + 8);
    int* cur_n = off_u + (MAXN + 8);
    int* cur_u = cur_n + MAXN;

    float* out_u = (float*)d_out;
    float* out_n = (float*)d_out + (long)NU * D;

    long MbU = (long)NU * 128, MbN = (long)NN * 128;

    // ---- one-time host-object setup (pre-baseline: first call is the
    // correctness run, before the harness takes its capture memory baseline) --
    static bool init_done = false;
    static cudaStream_t s1, s2;
    static cudaEvent_t evFork, evSortE1, evSortE2, evOpsN, evOpsU, evWc, evZrN, evHRu, evJoin;
    if (!init_done) {
        cudaFuncSetAttribute(gemm_mma, cudaFuncAttributeMaxDynamicSharedMemorySize, 98304);
        cudaStreamCreateWithFlags(&s1, cudaStreamNonBlocking);
        cudaStreamCreateWithFlags(&s2, cudaStreamNonBlocking);
        cudaEventCreateWithFlags(&evFork, cudaEventDisableTiming);
        cudaEventCreateWithFlags(&evSortE1, cudaEventDisableTiming);
        cudaEventCreateWithFlags(&evSortE2, cudaEventDisableTiming);
        cudaEventCreateWithFlags(&evOpsN, cudaEventDisableTiming);
        cudaEventCreateWithFlags(&evOpsU, cudaEventDisableTiming);
        cudaEventCreateWithFlags(&evWc, cudaEventDisableTiming);
        cudaEventCreateWithFlags(&evZrN, cudaEventDisableTiming);
        cudaEventCreateWithFlags(&evHRu, cudaEventDisableTiming);
        cudaEventCreateWithFlags(&evJoin, cudaEventDisableTiming);
        init_done = true;
    }

    // ===== capture fork =====
    cudaEventRecord(evFork, 0);
    cudaStreamWaitEvent(s1, evFork, 0);
    cudaStreamWaitEvent(s2, evFork, 0);

    // ===== S2: all packing, ordered by consumer priority =====
    pack_hi<<<(NN * 32 + 255) / 256, 256, 0, s2>>>(x_news, NN, packP(1));
    pack_hi<<<(NN * 32 + 255) / 256, 256, 0, s2>>>(h_news, NN, packP(3));
    pack_w_zr<<<512, 256, 0, s2>>>(Wl, Wr, WzrN, 0);
    build_bias<<<1, 128, 0, s2>>>(bb, bzr_n, bzr_u, bc_n, bc_u);
    cudaEventRecord(evOpsN, s2);
    pack_hi<<<(NU * 32 + 255) / 256, 256, 0, s2>>>(x_user, NU, packP(0));
    pack_hi<<<(NU * 32 + 255) / 256, 256, 0, s2>>>(h_user, NU, packP(2));
    pack_w_zr<<<512, 256, 0, s2>>>(Wl, Wr, WzrU, 1);
    cudaEventRecord(evOpsU, s2);
    pack_w2<<<128, 256, 0, s2>>>(Wl, Wr, WcN, 4, 0, 0);
    pack_w2<<<128, 256, 0, s2>>>(Wl, Wr, WcN, 5, 0, 2);
    pack_w2<<<128, 256, 0, s2>>>(Wl, Wr, WcU, 4, 1, 0);
    pack_w2<<<128, 256, 0, s2>>>(Wl, Wr, WcU, 5, 1, 2);
    cudaEventRecord(evWc, s2);

    // ===== S0: sort E1, gather news (fp32 direct), zrN =====
    zero_int<<<(MAXN + 255) / 256, 256>>>(deg_n, MAXN);
    count_deg<<<(E1 + 255) / 256, 256>>>(dst_un, E1, deg_n);
    scan_kernel<<<1, 1024>>>(deg_n, NN, off_n, cur_n);
    scatter_kernel<<<(E1 + 255) / 256, 256>>>(src_un, dst_un, E1, cur_n, ssrc1);
    cudaEventRecord(evSortE1, 0);
    gather2_f<<<(NN * 32 + 255) / 256, 256>>>(x_user, h_user, off_n, ssrc1, NN,
                                              packP(4), packP(5), MbN);
    cudaStreamWaitEvent(0, evOpsN, 0);
    {
        GP g{};
        g.hi[0] = packP(4); g.hi[1] = packP(1); g.hi[2] = packP(5); g.hi[3] = packP(3);
        g.B = WzrN; g.bias = bzr_n; g.H = h_news; g.out0 = Zn; g.outHR = packP(10);
        g.Mb = MbN; g.M = NN; g.N = 256; g.nparts = 4; g.mode = 0;
        gemm_mma<<<dim3((NN + 127) / 128, 2), 256, 98304>>>(g);
    }
    cudaEventRecord(evZrN, 0);

    // ===== S1: sort E2 (concurrent), gather user, zrU =====
    zero_int<<<(MAXN + 255) / 256, 256, 0, s1>>>(deg_u, MAXN);
    count_deg<<<(E2 + 255) / 256, 256, 0, s1>>>(dst_nu, E2, deg_u);
    scan_kernel<<<1, 1024, 0, s1>>>(deg_u, NU, off_u, cur_u);
    scatter_kernel<<<(E2 + 255) / 256, 256, 0, s1>>>(src_nu, dst_nu, E2, cur_u, ssrc2);
    cudaEventRecord(evSortE2, s1);
    gather2_f<<<(NU * 32 + 255) / 256, 256, 0, s1>>>(x_news, h_news, off_u, ssrc2, NU,
                                                     packP(6), packP(7), MbU);
    cudaStreamWaitEvent(s1, evOpsU, 0);
    {
        GP g{};
        g.hi[0] = packP(6); g.hi[1] = packP(0); g.hi[2] = packP(7); g.hi[3] = packP(2);
        g.B = WzrU; g.bias = bzr_u; g.H = h_user; g.out0 = Zu; g.outHR = packP(11);
        g.Mb = MbU; g.M = NU; g.N = 256; g.nparts = 4; g.mode = 0;
        gemm_mma<<<dim3((NU + 127) / 128, 2), 256, 98304, s1>>>(g);
    }
    cudaEventRecord(evHRu, s1);

    // ===== S0: gather1 E2 (PHRN -> PACU), chU -> out_u =====
    cudaStreamWaitEvent(0, evSortE2, 0);
    gather1_p<<<(NU * 32 + 255) / 256, 256>>>(packP(10), MbN, off_u, ssrc2, NU,
                                              packP(9), MbU);
    cudaStreamWaitEvent(0, evHRu, 0);
    cudaStreamWaitEvent(0, evWc, 0);
    {
        GP g{};
        g.hi[0] = packP(6); g.hi[1] = packP(0); g.hi[2] = packP(9); g.hi[3] = packP(11);
        g.B = WcU; g.bias = bc_u; g.H = h_user; g.Z = Zu; g.out0 = out_u;
        g.Mb = MbU; g.M = NU; g.N = 128; g.nparts = 4; g.mode = 2;
        gemm_mma<<<dim3((NU + 127) / 128, 1), 256, 98304>>>(g);
    }

    // ===== S1: gather1 E1 (PHRU -> PACN), chN -> out_n =====
    cudaStreamWaitEvent(s1, evSortE1, 0);
    gather1_p<<<(NN * 32 + 255) / 256, 256, 0, s1>>>(packP(11), MbU, off_n, ssrc1, NN,
                                                     packP(8), MbN);
    cudaStreamWaitEvent(s1, evZrN, 0);
    cudaStreamWaitEvent(s1, evWc, 0);
    {
        GP g{};
        g.hi[0] = packP(4); g.hi[1] = packP(1); g.hi[2] = packP(8); g.hi[3] = packP(10);
        g.B = WcN; g.bias = bc_n; g.H = h_news; g.Z = Zn; g.out0 = out_n;
        g.Mb = MbN; g.M = NN; g.N = 128; g.nparts = 4; g.mode = 2;
        gemm_mma<<<dim3((NN + 127) / 128, 1), 256, 98304, s1>>>(g);
    }
    cudaEventRecord(evJoin, s1);

    // ===== join =====
    cudaStreamWaitEvent(0, evJoin, 0);
}

// round 15
// speedup vs baseline: 1.0278x; 1.0278x over previous
#include <cuda_runtime.h>
#include <cuda_fp16.h>
#include <math.h>
#include <stdint.h>

#define D 128
#define MAXN 50000
#define MAXE 1000000
#define SZF (50000L * 128L)

__device__ float g_buf[22L * SZF + 2 * 131072 + 4 * 32768 + 1024];
__device__ int g_deg[2 * MAXN];
__device__ int g_idx[2 * MAXE + 2 * (MAXN + 8) + 2 * MAXN];

// ---------------- helpers ----------------
__device__ __forceinline__ uint32_t s2u(const void* p) {
    uint32_t a;
    asm("{ .reg .u64 t; cvta.to.shared.u64 t, %1; cvt.u32.u64 %0, t; }" : "=r"(a) : "l"(p));
    return a;
}
__device__ __host__ __forceinline__ uint32_t SWZ(uint32_t x) { return x ^ ((x >> 3) & 0x70); }

__device__ __forceinline__ float sigf(float x) { return 1.f / (1.f + expf(-x)); }

__device__ __forceinline__ uint2 pack4_hi(float4 v) {
    __half2 a = __floats2half2_rn(v.x, v.y);
    __half2 b = __floats2half2_rn(v.z, v.w);
    uint2 r;
    r.x = *reinterpret_cast<uint32_t*>(&a);
    r.y = *reinterpret_cast<uint32_t*>(&b);
    return r;
}

__device__ __forceinline__ void acc_u2(float4& s, uint2 v) {
    float2 p0 = __half22float2(*reinterpret_cast<__half2*>(&v.x));
    float2 p1 = __half22float2(*reinterpret_cast<__half2*>(&v.y));
    s.x += p0.x; s.y += p0.y; s.z += p1.x; s.w += p1.y;
}

// ---------------- sort-by-destination ----------------
__global__ void zero_int(int* p, int n) {
    int i = blockIdx.x * blockDim.x + threadIdx.x;
    if (i < n) p[i] = 0;
}

__global__ void count_deg(const int* __restrict__ dst, int E, int* __restrict__ deg) {
    int i = blockIdx.x * blockDim.x + threadIdx.x;
    if (i < E) atomicAdd(&deg[dst[i]], 1);
}

__global__ void scan_kernel(const int* __restrict__ deg, int n,
                            int* __restrict__ off, int* __restrict__ cur) {
    __shared__ int wsum[32];
    __shared__ int carry;
    int tid = threadIdx.x, lane = tid & 31, w = tid >> 5;
    if (tid == 0) { carry = 0; off[0] = 0; }
    __syncthreads();
    for (int base = 0; base < n; base += 1024) {
        int i = base + tid;
        int v = (i < n) ? deg[i] : 0;
        int x = v;
#pragma unroll
        for (int o = 1; o < 32; o <<= 1) {
            int y = __shfl_up_sync(0xFFFFFFFFu, x, o);
            if (lane >= o) x += y;
        }
        if (lane == 31) wsum[w] = x;
        __syncthreads();
        if (w == 0) {
            int s = wsum[lane];
#pragma unroll
            for (int o = 1; o < 32; o <<= 1) {
                int y = __shfl_up_sync(0xFFFFFFFFu, s, o);
                if (lane >= o) s += y;
            }
            wsum[lane] = s;
        }
        __syncthreads();
        int incl = x + (w ? wsum[w - 1] : 0) + carry;
        if (i < n) { off[i + 1] = incl; cur[i] = incl - v; }
        __syncthreads();
        if (tid == 1023) carry = incl;
        __syncthreads();
    }
}

__global__ void scatter_kernel(const int* __restrict__ src, const int* __restrict__ dst,
                               int E, int* __restrict__ cur, int* __restrict__ ssrc) {
    int i = blockIdx.x * blockDim.x + threadIdx.x;
    if (i < E) {
        int pos = atomicAdd(&cur[dst[i]], 1);
        ssrc[pos] = src[i];
    }
}

// ---------------- packing ----------------
__global__ void pack_hi(const float* __restrict__ src, int M, char* __restrict__ dst) {
    long i = blockIdx.x * (long)blockDim.x + threadIdx.x;
    if (i >= (long)M * 32) return;
    int row = (int)(i >> 5);
    int c4 = ((int)i & 31) * 4;
    float4 v = ((const float4*)src)[i];
    uint2 hu = pack4_hi(v);
    int q = c4 >> 6;
    int inner = c4 & 63;
    uint32_t sw = SWZ((uint32_t)row * 128u + (uint32_t)inner * 2u);
    long Mb = (long)M * 128;
    *(uint2*)(dst + (long)q * Mb + sw) = hu;
}

// pull aggregation from packed fp16 tables, warp-per-node, unroll x4
__global__ void gather2_p(const char* __restrict__ Px, const char* __restrict__ Ph, long MbS,
                          const int* __restrict__ off, const int* __restrict__ ssrc, int n,
                          char* __restrict__ Ox, char* __restrict__ Oh, long MbD) {
    long gid = blockIdx.x * (long)blockDim.x + threadIdx.x;
    int node = (int)(gid >> 5), lane = (int)(gid & 31);
    if (node >= n) return;
    int s0 = off[node], s1 = off[node + 1];
    int c4 = lane * 4;
    int q = c4 >> 6;
    int inner = c4 & 63;
    long qb = (long)q * MbS;
    float4 sx = make_float4(0.f, 0.f, 0.f, 0.f);
    float4 sh = make_float4(0.f, 0.f, 0.f, 0.f);
    int i = s0;
    for (; i + 3 < s1; i += 4) {
        int a0 = ssrc[i], a1 = ssrc[i + 1], a2 = ssrc[i + 2], a3 = ssrc[i + 3];
        uint32_t w0 = SWZ((uint32_t)a0 * 128u + (uint32_t)inner * 2u);
        uint32_t w1 = SWZ((uint32_t)a1 * 128u + (uint32_t)inner * 2u);
        uint32_t w2 = SWZ((uint32_t)a2 * 128u + (uint32_t)inner * 2u);
        uint32_t w3 = SWZ((uint32_t)a3 * 128u + (uint32_t)inner * 2u);
        uint2 x0 = *(const uint2*)(Px + qb + w0);
        uint2 x1 = *(const uint2*)(Px + qb + w1);
        uint2 x2 = *(const uint2*)(Px + qb + w2);
        uint2 x3 = *(const uint2*)(Px + qb + w3);
        uint2 h0 = *(const uint2*)(Ph + qb + w0);
        uint2 h1 = *(const uint2*)(Ph + qb + w1);
        uint2 h2 = *(const uint2*)(Ph + qb + w2);
        uint2 h3 = *(const uint2*)(Ph + qb + w3);
        acc_u2(sx, x0); acc_u2(sx, x1); acc_u2(sx, x2); acc_u2(sx, x3);
        acc_u2(sh, h0); acc_u2(sh, h1); acc_u2(sh, h2); acc_u2(sh, h3);
    }
    for (; i < s1; i++) {
        int a = ssrc[i];
        uint32_t w0 = SWZ((uint32_t)a * 128u + (uint32_t)inner * 2u);
        acc_u2(sx, *(const uint2*)(Px + qb + w0));
        acc_u2(sh, *(const uint2*)(Ph + qb + w0));
    }
    float inv = 1.f / (float)max(s1 - s0, 1);
    sx.x *= inv; sx.y *= inv; sx.z *= inv; sx.w *= inv;
    sh.x *= inv; sh.y *= inv; sh.z *= inv; sh.w *= inv;
    uint32_t swd = SWZ((uint32_t)node * 128u + (uint32_t)inner * 2u);
    *(uint2*)(Ox + (long)q * MbD + swd) = pack4_hi(sx);
    *(uint2*)(Oh + (long)q * MbD + swd) = pack4_hi(sh);
}

__global__ void gather1_p(const char* __restrict__ P, long MbS,
                          const int* __restrict__ off, const int* __restrict__ ssrc, int n,
                          char* __restrict__ dstP, long MbD) {
    long gid = blockIdx.x * (long)blockDim.x + threadIdx.x;
    int node = (int)(gid >> 5), lane = (int)(gid & 31);
    if (node >= n) return;
    int s0 = off[node], s1 = off[node + 1];
    int c4 = lane * 4;
    int q = c4 >> 6;
    int inner = c4 & 63;
    long qb = (long)q * MbS;
    float4 acc = make_float4(0.f, 0.f, 0.f, 0.f);
    int i = s0;
    for (; i + 3 < s1; i += 4) {
        int a0 = ssrc[i], a1 = ssrc[i + 1], a2 = ssrc[i + 2], a3 = ssrc[i + 3];
        uint2 v0 = *(const uint2*)(P + qb + SWZ((uint32_t)a0 * 128u + (uint32_t)inner * 2u));
        uint2 v1 = *(const uint2*)(P + qb + SWZ((uint32_t)a1 * 128u + (uint32_t)inner * 2u));
        uint2 v2 = *(const uint2*)(P + qb + SWZ((uint32_t)a2 * 128u + (uint32_t)inner * 2u));
        uint2 v3 = *(const uint2*)(P + qb + SWZ((uint32_t)a3 * 128u + (uint32_t)inner * 2u));
        acc_u2(acc, v0); acc_u2(acc, v1); acc_u2(acc, v2); acc_u2(acc, v3);
    }
    for (; i < s1; i++) {
        int a = ssrc[i];
        acc_u2(acc, *(const uint2*)(P + qb + SWZ((uint32_t)a * 128u + (uint32_t)inner * 2u)));
    }
    float inv = 1.f / (float)max(s1 - s0, 1);
    acc.x *= inv; acc.y *= inv; acc.z *= inv; acc.w *= inv;
    uint32_t swd = SWZ((uint32_t)node * 128u + (uint32_t)inner * 2u);
    *(uint2*)(dstP + (long)q * MbD + swd) = pack4_hi(acc);
}

// ---------------- weight packing (fp16) ----------------
__global__ void pack_w_zr(const float* __restrict__ Wl, const float* __restrict__ Wr,
                          char* __restrict__ dst, int t) {
    int j = blockIdx.x * blockDim.x + threadIdx.x;
    if (j >= 4 * 256 * 128) return;
    int k = j & 127;
    int n = (j >> 7) & 255;
    int p = j >> 15;
    int gz = (n < 128) ? 0 : 2;
    int cc = n & 127;
    int g = gz + (p >> 1);
    const float* S = (p & 1) ? Wr : Wl;
    float w = S[((long)(g * 2 + t) * 128 + k) * 128 + cc];
    __half h = __float2half_rn(w);
    int q = k >> 6;
    int inner = k & 63;
    uint32_t sw = SWZ((uint32_t)n * 128u + (uint32_t)inner * 2u);
    const int Nb = 256 * 128;
    *(unsigned short*)(dst + (size_t)(p * 2 + q) * Nb + sw) = *reinterpret_cast<unsigned short*>(&h);
}

__global__ void pack_w2(const float* __restrict__ Wl, const float* __restrict__ Wr,
                        char* __restrict__ dst, int g, int t, int pbase) {
    int j = blockIdx.x * blockDim.x + threadIdx.x;
    if (j >= 2 * 128 * 128) return;
    int k = j & 127;
    int n = (j >> 7) & 127;
    int p = j >> 14;
    const float* S = p ? Wr : Wl;
    float w = S[((long)(g * 2 + t) * 128 + k) * 128 + n];
    __half h = __float2half_rn(w);
    int q = k >> 6;
    int inner = k & 63;
    uint32_t sw = SWZ((uint32_t)n * 128u + (uint32_t)inner * 2u);
    const int Nb = 128 * 128;
    *(unsigned short*)(dst + (size_t)((pbase + p) * 2 + q) * Nb + sw) = *reinterpret_cast<unsigned short*>(&h);
}

__global__ void build_bias(const float* __restrict__ b,
                           float* bzr_n, float* bzr_u, float* bc_n, float* bc_u) {
    int c = threadIdx.x;
    if (c >= 128) return;
#define BB(g, t) b[((g) * 2 + (t)) * 128 + c]
    bzr_n[c]       = BB(0, 0) + BB(1, 0);
    bzr_n[128 + c] = BB(2, 0) + BB(3, 0);
    bzr_u[c]       = BB(0, 1) + BB(1, 1);
    bzr_u[128 + c] = BB(2, 1) + BB(3, 1);
    bc_n[c] = BB(4, 0) + BB(5, 0);
    bc_u[c] = BB(4, 1) + BB(5, 1);
#undef BB
}

// ---------------- HMMA GEMM (round-10 config: 256 thr, 4x2 warps) ----------
struct GP {
    const char* hi[4];
    const char* B;
    const float* bias;
    const float* H;
    const char* Zp;     // packed fp16 Z (mode 2 input)
    float* out0;
    char* outHR;
    char* outZ;         // packed fp16 Z (mode 0 output)
    long Mb;
    int M, N, nparts, mode;   // mode 0=zr, 2=ch
};

__device__ __forceinline__ void epi_pair(const GP& g, int row, int c, float v0, float v1) {
    v0 += g.bias[c];
    v1 += g.bias[c + 1];
    long rb = (long)row * D;
    if (g.mode == 0) {
        if (c < 128) {
            __half2 h = __floats2half2_rn(sigf(v0), sigf(v1));
            uint32_t sw = SWZ((uint32_t)row * 128u + (uint32_t)(c & 63) * 2u);
            int q = c >> 6;
            *(uint32_t*)(g.outZ + (long)q * g.Mb + sw) = *reinterpret_cast<uint32_t*>(&h);
        } else {
            int cc = c - 128;
            float r0 = sigf(v0) * g.H[rb + cc];
            float r1 = sigf(v1) * g.H[rb + cc + 1];
            __half2 h = __floats2half2_rn(r0, r1);
            uint32_t sw = SWZ((uint32_t)row * 128u + (uint32_t)(cc & 63) * 2u);
            int q = cc >> 6;
            *(uint32_t*)(g.outHR + (long)q * g.Mb + sw) = *reinterpret_cast<uint32_t*>(&h);
        }
    } else {
        uint32_t zb = *(const uint32_t*)(g.Zp + (long)(c >> 6) * g.Mb +
                                         SWZ((uint32_t)row * 128u + (uint32_t)(c & 63) * 2u));
        float2 z = __half22float2(*reinterpret_cast<__half2*>(&zb));
        float h0 = g.H[rb + c], h1 = g.H[rb + c + 1];
        float t0 = tanhf(v0);
        float t1 = tanhf(v1);
        g.out0[rb + c] = z.x * h0 + (1.f - z.x) * t0;
        g.out0[rb + c + 1] = z.y * h1 + (1.f - z.y) * t1;
    }
}

__global__ void __launch_bounds__(256) gemm_mma(GP g) {
    extern __shared__ char smem[];
    uint32_t sb = s2u(smem);
    int tid = threadIdx.x;
    int lane = tid & 31, wid = tid >> 5;
    int wm = wid & 3, wn = wid >> 2;
    int row0 = blockIdx.x * 128;
    int col0 = blockIdx.y * 128;
    long Nb = (long)g.N * 128;
    int C = g.nparts * 2;

    float acc[2][8][4];
#pragma unroll
    for (int i = 0; i < 2; i++)
#pragma unroll
        for (int j = 0; j < 8; j++)
#pragma unroll
            for (int k = 0; k < 4; k++) acc[i][j][k] = 0.f;

    auto issue = [&](int t) {
        int buf = t % 3;
        int p = t >> 1, q = t & 1;
        const char* Asrc = g.hi[p] + (long)q * g.Mb + (long)row0 * 128;
        const char* Bsrc = g.B + (size_t)(p * 2 + q) * Nb + (long)col0 * 128;
        uint32_t Ad = sb + (uint32_t)buf * 32768u;
        uint32_t Bd = Ad + 16384u;
#pragma unroll
        for (int j = 0; j < 4; j++) {
            int idx = tid + j * 256;
            uint32_t sz = (row0 + (idx >> 3) < g.M) ? 16u : 0u;
            asm volatile("cp.async.cg.shared.global [%0], [%1], 16, %2;"
                         :: "r"(Ad + idx * 16), "l"(Asrc + (long)idx * 16), "r"(sz));
        }
#pragma unroll
        for (int j = 0; j < 4; j++) {
            int idx = tid + j * 256;
            asm volatile("cp.async.cg.shared.global [%0], [%1], 16;"
                         :: "r"(Bd + idx * 16), "l"(Bsrc + (long)idx * 16));
        }
        asm volatile("cp.async.commit_group;" ::: "memory");
    };

    issue(0);
    issue(1);
    issue(2);

    for (int t = 0; t < C; t++) {
        int rem = C - t;
        if (rem > 2)       asm volatile("cp.async.wait_group 2;" ::: "memory");
        else if (rem == 2) asm volatile("cp.async.wait_group 1;" ::: "memory");
        else               asm volatile("cp.async.wait_group 0;" ::: "memory");
        __syncthreads();
        uint32_t Ab = sb + (uint32_t)(t % 3) * 32768u;
        uint32_t Bb = Ab + 16384u;
#pragma unroll
        for (int kk = 0; kk < 4; kk++) {
            uint32_t a[2][4];
#pragma unroll
            for (int mi = 0; mi < 2; mi++) {
                int rr = wm * 32 + mi * 16 + (lane & 15);
                int byt = kk * 32 + ((lane >> 4) << 4);
                uint32_t ad = Ab + SWZ((uint32_t)(rr * 128 + byt));
                asm volatile("ldmatrix.sync.aligned.m8n8.x4.shared.b16 {%0,%1,%2,%3}, [%4];"
                    : "=r"(a[mi][0]), "=r"(a[mi][1]), "=r"(a[mi][2]), "=r"(a[mi][3])
                    : "r"(ad));
            }
            uint32_t b[8][2];
#pragma unroll
            for (int nj = 0; nj < 4; nj++) {
                int nn = wn * 64 + nj * 16 + ((lane >> 4) << 3) + (lane & 7);
                int byt = kk * 32 + (((lane >> 3) & 1) << 4);
                uint32_t bd2 = Bb + SWZ((uint32_t)(nn * 128 + byt));
                asm volatile("ldmatrix.sync.aligned.m8n8.x4.shared.b16 {%0,%1,%2,%3}, [%4];"
                    : "=r"(b[nj * 2][0]), "=r"(b[nj * 2][1]),
                      "=r"(b[nj * 2 + 1][0]), "=r"(b[nj * 2 + 1][1])
                    : "r"(bd2));
            }
#pragma unroll
            for (int mi = 0; mi < 2; mi++)
#pragma unroll
                for (int ni = 0; ni < 8; ni++) {
                    asm volatile(
                        "mma.sync.aligned.m16n8k16.row.col.f32.f16.f16.f32 "
                        "{%0,%1,%2,%3}, {%4,%5,%6,%7}, {%8,%9}, {%0,%1,%2,%3};"
                        : "+f"(acc[mi][ni][0]), "+f"(acc[mi][ni][1]),
                          "+f"(acc[mi][ni][2]), "+f"(acc[mi][ni][3])
                        : "r"(a[mi][0]), "r"(a[mi][1]), "r"(a[mi][2]), "r"(a[mi][3]),
                          "r"(b[ni][0]), "r"(b[ni][1]));
                }
        }
        __syncthreads();
        if (t + 3 < C) issue(t + 3);
    }

    int lr = lane >> 2, lc = (lane & 3) * 2;
#pragma unroll
    for (int mi = 0; mi < 2; mi++)
#pragma unroll
        for (int half = 0; half < 2; half++) {
            int row = row0 + wm * 32 + mi * 16 + half * 8 + lr;
            if (row < g.M) {
#pragma unroll
                for (int ni = 0; ni < 8; ni++) {
                    int c = col0 + wn * 64 + ni * 8 + lc;
                    epi_pair(g, row, c, acc[mi][ni][half * 2], acc[mi][ni][half * 2 + 1]);
                }
            }
        }
}

// ---------------------------------------------------------------------------
extern "C" void kernel_launch(void* const* d_in, const int* in_sizes, int n_in,
                              void* d_out, int out_size) {
    const float* x_user = (const float*)d_in[0];
    const float* x_news = (const float*)d_in[1];
    const float* h_user = (const float*)d_in[2];
    const float* h_news = (const float*)d_in[3];
    const float* Wl     = (const float*)d_in[4];
    const float* Wr     = (const float*)d_in[5];
    const float* bb     = (const float*)d_in[6];
    const int* src_un   = (const int*)d_in[7];
    const int* dst_un   = (const int*)d_in[8];
    const int* src_nu   = (const int*)d_in[9];
    const int* dst_nu   = (const int*)d_in[10];

    int NU = in_sizes[0] / D;
    int NN = in_sizes[1] / D;
    int E1 = in_sizes[7];
    int E2 = in_sizes[9];

    float* base = nullptr;
    int* deg = nullptr;
    int* idx = nullptr;
    cudaGetSymbolAddress((void**)&base, g_buf);
    cudaGetSymbolAddress((void**)&deg, g_deg);
    cudaGetSymbolAddress((void**)&idx, g_idx);

    char* Zpn = (char*)(base + 6 * SZF);   // packed fp16 Z (news)
    char* Zpu = (char*)(base + 7 * SZF);   // packed fp16 Z (user)
    auto packP = [&](int i) -> char* { return (char*)(base + (10L + i) * SZF); };

    float* wf = base + 22 * SZF;
    char* WzrN = (char*)(wf);
    char* WzrU = (char*)(wf + 131072);
    char* WcN  = (char*)(wf + 262144);
    char* WcU  = (char*)(wf + 262144 + 32768);
    float* bzr_n = wf + 262144 + 4 * 32768;
    float* bzr_u = bzr_n + 256;
    float* bc_n  = bzr_u + 256;
    float* bc_u  = bc_n + 128;

    int* deg_n = deg;
    int* deg_u = deg + MAXN;
    int* ssrc1 = idx;
    int* ssrc2 = idx + MAXE;
    int* off_n = idx + 2 * MAXE;
    int* off_u = off_n + (MAXN + 8);
    int* cur_n = off_u + (MAXN + 8);
    int* cur_u = cur_n + MAXN;

    float* out_u = (float*)d_out;
    float* out_n = (float*)d_out + (long)NU * D;

    long MbU = (long)NU * 128, MbN = (long)NN * 128;

    // ---- one-time host-object setup (first call precedes capture baseline) --
    static bool init_done = false;
    static cudaStream_t s1;
    static cudaEvent_t evFork, evPackXH, evWzrN, evSortE1, evSortE2, evZrN, evHRu, evJoin;
    if (!init_done) {
        cudaFuncSetAttribute(gemm_mma, cudaFuncAttributeMaxDynamicSharedMemorySize, 98304);
        cudaStreamCreateWithFlags(&s1, cudaStreamNonBlocking);
        cudaEventCreateWithFlags(&evFork, cudaEventDisableTiming);
        cudaEventCreateWithFlags(&evPackXH, cudaEventDisableTiming);
        cudaEventCreateWithFlags(&evWzrN, cudaEventDisableTiming);
        cudaEventCreateWithFlags(&evSortE1, cudaEventDisableTiming);
        cudaEventCreateWithFlags(&evSortE2, cudaEventDisableTiming);
        cudaEventCreateWithFlags(&evZrN, cudaEventDisableTiming);
        cudaEventCreateWithFlags(&evHRu, cudaEventDisableTiming);
        cudaEventCreateWithFlags(&evJoin, cudaEventDisableTiming);
        init_done = true;
    }

    // ===== capture fork =====
    cudaEventRecord(evFork, 0);
    cudaStreamWaitEvent(s1, evFork, 0);

    // ===== S0: sort E1 =====
    zero_int<<<(MAXN + 255) / 256, 256>>>(deg_n, MAXN);
    count_deg<<<(E1 + 255) / 256, 256>>>(dst_un, E1, deg_n);
    scan_kernel<<<1, 1024>>>(deg_n, NN, off_n, cur_n);
    scatter_kernel<<<(E1 + 255) / 256, 256>>>(src_un, dst_un, E1, cur_n, ssrc1);
    cudaEventRecord(evSortE1, 0);

    // ===== S1: input packs, zrN-critical weights first, then the rest =====
    pack_hi<<<(NU * 32 + 255) / 256, 256, 0, s1>>>(x_user, NU, packP(0));
    pack_hi<<<(NN * 32 + 255) / 256, 256, 0, s1>>>(x_news, NN, packP(1));
    pack_hi<<<(NU * 32 + 255) / 256, 256, 0, s1>>>(h_user, NU, packP(2));
    pack_hi<<<(NN * 32 + 255) / 256, 256, 0, s1>>>(h_news, NN, packP(3));
    cudaEventRecord(evPackXH, s1);
    pack_w_zr<<<512, 256, 0, s1>>>(Wl, Wr, WzrN, 0);
    build_bias<<<1, 128, 0, s1>>>(bb, bzr_n, bzr_u, bc_n, bc_u);
    cudaEventRecord(evWzrN, s1);
    pack_w_zr<<<512, 256, 0, s1>>>(Wl, Wr, WzrU, 1);
    pack_w2<<<128, 256, 0, s1>>>(Wl, Wr, WcN, 4, 0, 0);
    pack_w2<<<128, 256, 0, s1>>>(Wl, Wr, WcN, 5, 0, 2);
    pack_w2<<<128, 256, 0, s1>>>(Wl, Wr, WcU, 4, 1, 0);
    pack_w2<<<128, 256, 0, s1>>>(Wl, Wr, WcU, 5, 1, 2);

    // ===== S0: gather news aggregates, zr news GEMM =====
    cudaStreamWaitEvent(0, evPackXH, 0);
    gather2_p<<<(NN * 32 + 255) / 256, 256>>>(packP(0), packP(2), MbU, off_n, ssrc1, NN,
                                              packP(4), packP(5), MbN);
    cudaStreamWaitEvent(0, evWzrN, 0);
    {
        GP g{};
        g.hi[0] = packP(4); g.hi[1] = packP(1); g.hi[2] = packP(5); g.hi[3] = packP(3);
        g.B = WzrN; g.bias = bzr_n; g.H = h_news; g.outZ = Zpn; g.outHR = packP(10);
        g.Mb = MbN; g.M = NN; g.N = 256; g.nparts = 4; g.mode = 0;
        gemm_mma<<<dim3((NN + 127) / 128, 2), 256, 98304>>>(g);
    }
    cudaEventRecord(evZrN, 0);

    // ===== S1: sort E2, gather user aggregates, zr user GEMM =====
    zero_int<<<(MAXN + 255) / 256, 256, 0, s1>>>(deg_u, MAXN);
    count_deg<<<(E2 + 255) / 256, 256, 0, s1>>>(dst_nu, E2, deg_u);
    scan_kernel<<<1, 1024, 0, s1>>>(deg_u, NU, off_u, cur_u);
    scatter_kernel<<<(E2 + 255) / 256, 256, 0, s1>>>(src_nu, dst_nu, E2, cur_u, ssrc2);
    cudaEventRecord(evSortE2, s1);
    gather2_p<<<(NU * 32 + 255) / 256, 256, 0, s1>>>(packP(1), packP(3), MbN, off_u, ssrc2, NU,
                                                     packP(6), packP(7), MbU);
    {
        GP g{};
        g.hi[0] = packP(6); g.hi[1] = packP(0); g.hi[2] = packP(7); g.hi[3] = packP(2);
        g.B = WzrU; g.bias = bzr_u; g.H = h_user; g.outZ = Zpu; g.outHR = packP(11);
        g.Mb = MbU; g.M = NU; g.N = 256; g.nparts = 4; g.mode = 0;
        gemm_mma<<<dim3((NU + 127) / 128, 2), 256, 98304, s1>>>(g);
    }
    cudaEventRecord(evHRu, s1);

    // ===== S0: gather1 E2 (PHRN -> PACU), chU GEMM -> out_u =====
    cudaStreamWaitEvent(0, evSortE2, 0);
    gather1_p<<<(NU * 32 + 255) / 256, 256>>>(packP(10), MbN, off_u, ssrc2, NU,
                                              packP(9), MbU);
    cudaStreamWaitEvent(0, evHRu, 0);
    {
        GP g{};
        g.hi[0] = packP(6); g.hi[1] = packP(0); g.hi[2] = packP(9); g.hi[3] = packP(11);
        g.B = WcU; g.bias = bc_u; g.H = h_user; g.Zp = Zpu; g.out0 = out_u;
        g.Mb = MbU; g.M = NU; g.N = 128; g.nparts = 4; g.mode = 2;
        gemm_mma<<<dim3((NU + 127) / 128, 1), 256, 98304>>>(g);
    }

    // ===== S1: gather1 E1 (PHRU -> PACN), chN GEMM -> out_n =====
    cudaStreamWaitEvent(s1, evSortE1, 0);
    gather1_p<<<(NN * 32 + 255) / 256, 256, 0, s1>>>(packP(11), MbU, off_n, ssrc1, NN,
                                                     packP(8), MbN);
    cudaStreamWaitEvent(s1, evZrN, 0);
    {
        GP g{};
        g.hi[0] = packP(4); g.hi[1] = packP(1); g.hi[2] = packP(8); g.hi[3] = packP(10);
        g.B = WcN; g.bias = bc_n; g.H = h_news; g.Zp = Zpn; g.out0 = out_n;
        g.Mb = MbN; g.M = NN; g.N = 128; g.nparts = 4; g.mode = 2;
        gemm_mma<<<dim3((NN + 127) / 128, 1), 256, 98304, s1>>>(g);
    }
    cudaEventRecord(evJoin, s1);

    // ===== join =====
    cudaStreamWaitEvent(0, evJoin, 0);
}

// round 16
// speedup vs baseline: 1.0520x; 1.0235x over previous
#include <cuda_runtime.h>
#include <cuda_fp16.h>
#include <math.h>
#include <stdint.h>

#define D 128
#define MAXN 50000
#define MAXE 1000000
#define SZF (50000L * 128L)

__device__ float g_buf[22L * SZF + 2 * 131072 + 4 * 32768 + 1024];
__device__ int g_deg[2 * MAXN];
__device__ int g_idx[2 * MAXE + 2 * (MAXN + 8) + 2 * MAXN];

// ---------------- helpers ----------------
__device__ __forceinline__ uint32_t s2u(const void* p) {
    uint32_t a;
    asm("{ .reg .u64 t; cvta.to.shared.u64 t, %1; cvt.u32.u64 %0, t; }" : "=r"(a) : "l"(p));
    return a;
}
__device__ __host__ __forceinline__ uint32_t SWZ(uint32_t x) { return x ^ ((x >> 3) & 0x70); }

__device__ __forceinline__ float sigf(float x) { return 1.f / (1.f + expf(-x)); }

__device__ __forceinline__ uint2 pack4_hi(float4 v) {
    __half2 a = __floats2half2_rn(v.x, v.y);
    __half2 b = __floats2half2_rn(v.z, v.w);
    uint2 r;
    r.x = *reinterpret_cast<uint32_t*>(&a);
    r.y = *reinterpret_cast<uint32_t*>(&b);
    return r;
}

__device__ __forceinline__ void acc_u2(float4& s, uint2 v) {
    float2 p0 = __half22float2(*reinterpret_cast<__half2*>(&v.x));
    float2 p1 = __half22float2(*reinterpret_cast<__half2*>(&v.y));
    s.x += p0.x; s.y += p0.y; s.z += p1.x; s.w += p1.y;
}

// ---------------- sort-by-destination ----------------
__global__ void zero_int(int* p, int n) {
    int i = blockIdx.x * blockDim.x + threadIdx.x;
    if (i < n) p[i] = 0;
}

__global__ void count_deg(const int* __restrict__ dst, int E, int* __restrict__ deg) {
    int i = blockIdx.x * blockDim.x + threadIdx.x;
    if (i < E) atomicAdd(&deg[dst[i]], 1);
}

__global__ void scan_kernel(const int* __restrict__ deg, int n,
                            int* __restrict__ off, int* __restrict__ cur) {
    __shared__ int wsum[32];
    __shared__ int carry;
    int tid = threadIdx.x, lane = tid & 31, w = tid >> 5;
    if (tid == 0) { carry = 0; off[0] = 0; }
    __syncthreads();
    for (int base = 0; base < n; base += 1024) {
        int i = base + tid;
        int v = (i < n) ? deg[i] : 0;
        int x = v;
#pragma unroll
        for (int o = 1; o < 32; o <<= 1) {
            int y = __shfl_up_sync(0xFFFFFFFFu, x, o);
            if (lane >= o) x += y;
        }
        if (lane == 31) wsum[w] = x;
        __syncthreads();
        if (w == 0) {
            int s = wsum[lane];
#pragma unroll
            for (int o = 1; o < 32; o <<= 1) {
                int y = __shfl_up_sync(0xFFFFFFFFu, s, o);
                if (lane >= o) s += y;
            }
            wsum[lane] = s;
        }
        __syncthreads();
        int incl = x + (w ? wsum[w - 1] : 0) + carry;
        if (i < n) { off[i + 1] = incl; cur[i] = incl - v; }
        __syncthreads();
        if (tid == 1023) carry = incl;
        __syncthreads();
    }
}

__global__ void scatter_kernel(const int* __restrict__ src, const int* __restrict__ dst,
                               int E, int* __restrict__ cur, int* __restrict__ ssrc) {
    int i = blockIdx.x * blockDim.x + threadIdx.x;
    if (i < E) {
        int pos = atomicAdd(&cur[dst[i]], 1);
        ssrc[pos] = src[i];
    }
}

// ---------------- packing ----------------
__global__ void pack_hi(const float* __restrict__ src, int M, char* __restrict__ dst) {
    long i = blockIdx.x * (long)blockDim.x + threadIdx.x;
    if (i >= (long)M * 32) return;
    int row = (int)(i >> 5);
    int c4 = ((int)i & 31) * 4;
    float4 v = ((const float4*)src)[i];
    uint2 hu = pack4_hi(v);
    int q = c4 >> 6;
    int inner = c4 & 63;
    uint32_t sw = SWZ((uint32_t)row * 128u + (uint32_t)inner * 2u);
    long Mb = (long)M * 128;
    *(uint2*)(dst + (long)q * Mb + sw) = hu;
}

// pull aggregation from packed fp16 tables, warp-per-node, unroll x4
__global__ void gather2_p(const char* __restrict__ Px, const char* __restrict__ Ph, long MbS,
                          const int* __restrict__ off, const int* __restrict__ ssrc, int n,
                          char* __restrict__ Ox, char* __restrict__ Oh, long MbD) {
    long gid = blockIdx.x * (long)blockDim.x + threadIdx.x;
    int node = (int)(gid >> 5), lane = (int)(gid & 31);
    if (node >= n) return;
    int s0 = off[node], s1 = off[node + 1];
    int c4 = lane * 4;
    int q = c4 >> 6;
    int inner = c4 & 63;
    long qb = (long)q * MbS;
    float4 sx = make_float4(0.f, 0.f, 0.f, 0.f);
    float4 sh = make_float4(0.f, 0.f, 0.f, 0.f);
    int i = s0;
    for (; i + 3 < s1; i += 4) {
        int a0 = ssrc[i], a1 = ssrc[i + 1], a2 = ssrc[i + 2], a3 = ssrc[i + 3];
        uint32_t w0 = SWZ((uint32_t)a0 * 128u + (uint32_t)inner * 2u);
        uint32_t w1 = SWZ((uint32_t)a1 * 128u + (uint32_t)inner * 2u);
        uint32_t w2 = SWZ((uint32_t)a2 * 128u + (uint32_t)inner * 2u);
        uint32_t w3 = SWZ((uint32_t)a3 * 128u + (uint32_t)inner * 2u);
        uint2 x0 = *(const uint2*)(Px + qb + w0);
        uint2 x1 = *(const uint2*)(Px + qb + w1);
        uint2 x2 = *(const uint2*)(Px + qb + w2);
        uint2 x3 = *(const uint2*)(Px + qb + w3);
        uint2 h0 = *(const uint2*)(Ph + qb + w0);
        uint2 h1 = *(const uint2*)(Ph + qb + w1);
        uint2 h2 = *(const uint2*)(Ph + qb + w2);
        uint2 h3 = *(const uint2*)(Ph + qb + w3);
        acc_u2(sx, x0); acc_u2(sx, x1); acc_u2(sx, x2); acc_u2(sx, x3);
        acc_u2(sh, h0); acc_u2(sh, h1); acc_u2(sh, h2); acc_u2(sh, h3);
    }
    for (; i < s1; i++) {
        int a = ssrc[i];
        uint32_t w0 = SWZ((uint32_t)a * 128u + (uint32_t)inner * 2u);
        acc_u2(sx, *(const uint2*)(Px + qb + w0));
        acc_u2(sh, *(const uint2*)(Ph + qb + w0));
    }
    float inv = 1.f / (float)max(s1 - s0, 1);
    sx.x *= inv; sx.y *= inv; sx.z *= inv; sx.w *= inv;
    sh.x *= inv; sh.y *= inv; sh.z *= inv; sh.w *= inv;
    uint32_t swd = SWZ((uint32_t)node * 128u + (uint32_t)inner * 2u);
    *(uint2*)(Ox + (long)q * MbD + swd) = pack4_hi(sx);
    *(uint2*)(Oh + (long)q * MbD + swd) = pack4_hi(sh);
}

__global__ void gather1_p(const char* __restrict__ P, long MbS,
                          const int* __restrict__ off, const int* __restrict__ ssrc, int n,
                          char* __restrict__ dstP, long MbD) {
    long gid = blockIdx.x * (long)blockDim.x + threadIdx.x;
    int node = (int)(gid >> 5), lane = (int)(gid & 31);
    if (node >= n) return;
    int s0 = off[node], s1 = off[node + 1];
    int c4 = lane * 4;
    int q = c4 >> 6;
    int inner = c4 & 63;
    long qb = (long)q * MbS;
    float4 acc = make_float4(0.f, 0.f, 0.f, 0.f);
    int i = s0;
    for (; i + 3 < s1; i += 4) {
        int a0 = ssrc[i], a1 = ssrc[i + 1], a2 = ssrc[i + 2], a3 = ssrc[i + 3];
        uint2 v0 = *(const uint2*)(P + qb + SWZ((uint32_t)a0 * 128u + (uint32_t)inner * 2u));
        uint2 v1 = *(const uint2*)(P + qb + SWZ((uint32_t)a1 * 128u + (uint32_t)inner * 2u));
        uint2 v2 = *(const uint2*)(P + qb + SWZ((uint32_t)a2 * 128u + (uint32_t)inner * 2u));
        uint2 v3 = *(const uint2*)(P + qb + SWZ((uint32_t)a3 * 128u + (uint32_t)inner * 2u));
        acc_u2(acc, v0); acc_u2(acc, v1); acc_u2(acc, v2); acc_u2(acc, v3);
    }
    for (; i < s1; i++) {
        int a = ssrc[i];
        acc_u2(acc, *(const uint2*)(P + qb + SWZ((uint32_t)a * 128u + (uint32_t)inner * 2u)));
    }
    float inv = 1.f / (float)max(s1 - s0, 1);
    acc.x *= inv; acc.y *= inv; acc.z *= inv; acc.w *= inv;
    uint32_t swd = SWZ((uint32_t)node * 128u + (uint32_t)inner * 2u);
    *(uint2*)(dstP + (long)q * MbD + swd) = pack4_hi(acc);
}

// ---------------- weight packing (fp16) ----------------
__global__ void pack_w_zr(const float* __restrict__ Wl, const float* __restrict__ Wr,
                          char* __restrict__ dst, int t) {
    int j = blockIdx.x * blockDim.x + threadIdx.x;
    if (j >= 4 * 256 * 128) return;
    int k = j & 127;
    int n = (j >> 7) & 255;
    int p = j >> 15;
    int gz = (n < 128) ? 0 : 2;
    int cc = n & 127;
    int g = gz + (p >> 1);
    const float* S = (p & 1) ? Wr : Wl;
    float w = S[((long)(g * 2 + t) * 128 + k) * 128 + cc];
    __half h = __float2half_rn(w);
    int q = k >> 6;
    int inner = k & 63;
    uint32_t sw = SWZ((uint32_t)n * 128u + (uint32_t)inner * 2u);
    const int Nb = 256 * 128;
    *(unsigned short*)(dst + (size_t)(p * 2 + q) * Nb + sw) = *reinterpret_cast<unsigned short*>(&h);
}

__global__ void pack_w2(const float* __restrict__ Wl, const float* __restrict__ Wr,
                        char* __restrict__ dst, int g, int t, int pbase) {
    int j = blockIdx.x * blockDim.x + threadIdx.x;
    if (j >= 2 * 128 * 128) return;
    int k = j & 127;
    int n = (j >> 7) & 127;
    int p = j >> 14;
    const float* S = p ? Wr : Wl;
    float w = S[((long)(g * 2 + t) * 128 + k) * 128 + n];
    __half h = __float2half_rn(w);
    int q = k >> 6;
    int inner = k & 63;
    uint32_t sw = SWZ((uint32_t)n * 128u + (uint32_t)inner * 2u);
    const int Nb = 128 * 128;
    *(unsigned short*)(dst + (size_t)((pbase + p) * 2 + q) * Nb + sw) = *reinterpret_cast<unsigned short*>(&h);
}

__global__ void build_bias(const float* __restrict__ b,
                           float* bzr_n, float* bzr_u, float* bc_n, float* bc_u) {
    int c = threadIdx.x;
    if (c >= 128) return;
#define BB(g, t) b[((g) * 2 + (t)) * 128 + c]
    bzr_n[c]       = BB(0, 0) + BB(1, 0);
    bzr_n[128 + c] = BB(2, 0) + BB(3, 0);
    bzr_u[c]       = BB(0, 1) + BB(1, 1);
    bzr_u[128 + c] = BB(2, 1) + BB(3, 1);
    bc_n[c] = BB(4, 0) + BB(5, 0);
    bc_u[c] = BB(4, 1) + BB(5, 1);
#undef BB
}

// ---------------- HMMA GEMM (round-10 config: 256 thr, 4x2 warps) ----------
struct GP {
    const char* hi[4];
    const char* B;
    const float* bias;
    const float* H;
    const char* Zp;     // packed fp16 Z (mode 2 input)
    float* out0;
    char* outHR;
    char* outZ;         // packed fp16 Z (mode 0 output)
    long Mb;
    int M, N, nparts, mode;   // mode 0=zr, 2=ch
};

__device__ __forceinline__ void epi_pair(const GP& g, int row, int c, float v0, float v1) {
    v0 += g.bias[c];
    v1 += g.bias[c + 1];
    long rb = (long)row * D;
    if (g.mode == 0) {
        if (c < 128) {
            __half2 h = __floats2half2_rn(sigf(v0), sigf(v1));
            uint32_t sw = SWZ((uint32_t)row * 128u + (uint32_t)(c & 63) * 2u);
            int q = c >> 6;
            *(uint32_t*)(g.outZ + (long)q * g.Mb + sw) = *reinterpret_cast<uint32_t*>(&h);
        } else {
            int cc = c - 128;
            float r0 = sigf(v0) * g.H[rb + cc];
            float r1 = sigf(v1) * g.H[rb + cc + 1];
            __half2 h = __floats2half2_rn(r0, r1);
            uint32_t sw = SWZ((uint32_t)row * 128u + (uint32_t)(cc & 63) * 2u);
            int q = cc >> 6;
            *(uint32_t*)(g.outHR + (long)q * g.Mb + sw) = *reinterpret_cast<uint32_t*>(&h);
        }
    } else {
        uint32_t zb = *(const uint32_t*)(g.Zp + (long)(c >> 6) * g.Mb +
                                         SWZ((uint32_t)row * 128u + (uint32_t)(c & 63) * 2u));
        float2 z = __half22float2(*reinterpret_cast<__half2*>(&zb));
        float h0 = g.H[rb + c], h1 = g.H[rb + c + 1];
        float t0 = tanhf(v0);
        float t1 = tanhf(v1);
        g.out0[rb + c] = z.x * h0 + (1.f - z.x) * t0;
        g.out0[rb + c + 1] = z.y * h1 + (1.f - z.y) * t1;
    }
}

__global__ void __launch_bounds__(256) gemm_mma(GP g) {
    extern __shared__ char smem[];
    uint32_t sb = s2u(smem);
    int tid = threadIdx.x;
    int lane = tid & 31, wid = tid >> 5;
    int wm = wid & 3, wn = wid >> 2;
    int row0 = blockIdx.x * 128;
    int col0 = blockIdx.y * 128;
    long Nb = (long)g.N * 128;
    int C = g.nparts * 2;

    float acc[2][8][4];
#pragma unroll
    for (int i = 0; i < 2; i++)
#pragma unroll
        for (int j = 0; j < 8; j++)
#pragma unroll
            for (int k = 0; k < 4; k++) acc[i][j][k] = 0.f;

    auto issue = [&](int t) {
        int buf = t % 3;
        int p = t >> 1, q = t & 1;
        const char* Asrc = g.hi[p] + (long)q * g.Mb + (long)row0 * 128;
        const char* Bsrc = g.B + (size_t)(p * 2 + q) * Nb + (long)col0 * 128;
        uint32_t Ad = sb + (uint32_t)buf * 32768u;
        uint32_t Bd = Ad + 16384u;
#pragma unroll
        for (int j = 0; j < 4; j++) {
            int idx = tid + j * 256;
            uint32_t sz = (row0 + (idx >> 3) < g.M) ? 16u : 0u;
            asm volatile("cp.async.cg.shared.global [%0], [%1], 16, %2;"
                         :: "r"(Ad + idx * 16), "l"(Asrc + (long)idx * 16), "r"(sz));
        }
#pragma unroll
        for (int j = 0; j < 4; j++) {
            int idx = tid + j * 256;
            asm volatile("cp.async.cg.shared.global [%0], [%1], 16;"
                         :: "r"(Bd + idx * 16), "l"(Bsrc + (long)idx * 16));
        }
        asm volatile("cp.async.commit_group;" ::: "memory");
    };

    issue(0);
    issue(1);
    issue(2);

    for (int t = 0; t < C; t++) {
        int rem = C - t;
        if (rem > 2)       asm volatile("cp.async.wait_group 2;" ::: "memory");
        else if (rem == 2) asm volatile("cp.async.wait_group 1;" ::: "memory");
        else               asm volatile("cp.async.wait_group 0;" ::: "memory");
        __syncthreads();
        uint32_t Ab = sb + (uint32_t)(t % 3) * 32768u;
        uint32_t Bb = Ab + 16384u;
#pragma unroll
        for (int kk = 0; kk < 4; kk++) {
            uint32_t a[2][4];
#pragma unroll
            for (int mi = 0; mi < 2; mi++) {
                int rr = wm * 32 + mi * 16 + (lane & 15);
                int byt = kk * 32 + ((lane >> 4) << 4);
                uint32_t ad = Ab + SWZ((uint32_t)(rr * 128 + byt));
                asm volatile("ldmatrix.sync.aligned.m8n8.x4.shared.b16 {%0,%1,%2,%3}, [%4];"
                    : "=r"(a[mi][0]), "=r"(a[mi][1]), "=r"(a[mi][2]), "=r"(a[mi][3])
                    : "r"(ad));
            }
            uint32_t b[8][2];
#pragma unroll
            for (int nj = 0; nj < 4; nj++) {
                int nn = wn * 64 + nj * 16 + ((lane >> 4) << 3) + (lane & 7);
                int byt = kk * 32 + (((lane >> 3) & 1) << 4);
                uint32_t bd2 = Bb + SWZ((uint32_t)(nn * 128 + byt));
                asm volatile("ldmatrix.sync.aligned.m8n8.x4.shared.b16 {%0,%1,%2,%3}, [%4];"
                    : "=r"(b[nj * 2][0]), "=r"(b[nj * 2][1]),
                      "=r"(b[nj * 2 + 1][0]), "=r"(b[nj * 2 + 1][1])
                    : "r"(bd2));
            }
#pragma unroll
            for (int mi = 0; mi < 2; mi++)
#pragma unroll
                for (int ni = 0; ni < 8; ni++) {
                    asm volatile(
                        "mma.sync.aligned.m16n8k16.row.col.f32.f16.f16.f32 "
                        "{%0,%1,%2,%3}, {%4,%5,%6,%7}, {%8,%9}, {%0,%1,%2,%3};"
                        : "+f"(acc[mi][ni][0]), "+f"(acc[mi][ni][1]),
                          "+f"(acc[mi][ni][2]), "+f"(acc[mi][ni][3])
                        : "r"(a[mi][0]), "r"(a[mi][1]), "r"(a[mi][2]), "r"(a[mi][3]),
                          "r"(b[ni][0]), "r"(b[ni][1]));
                }
        }
        __syncthreads();
        if (t + 3 < C) issue(t + 3);
    }

    int lr = lane >> 2, lc = (lane & 3) * 2;
#pragma unroll
    for (int mi = 0; mi < 2; mi++)
#pragma unroll
        for (int half = 0; half < 2; half++) {
            int row = row0 + wm * 32 + mi * 16 + half * 8 + lr;
            if (row < g.M) {
#pragma unroll
                for (int ni = 0; ni < 8; ni++) {
                    int c = col0 + wn * 64 + ni * 8 + lc;
                    epi_pair(g, row, c, acc[mi][ni][half * 2], acc[mi][ni][half * 2 + 1]);
                }
            }
        }
}

// ---------------------------------------------------------------------------
extern "C" void kernel_launch(void* const* d_in, const int* in_sizes, int n_in,
                              void* d_out, int out_size) {
    const float* x_user = (const float*)d_in[0];
    const float* x_news = (const float*)d_in[1];
    const float* h_user = (const float*)d_in[2];
    const float* h_news = (const float*)d_in[3];
    const float* Wl     = (const float*)d_in[4];
    const float* Wr     = (const float*)d_in[5];
    const float* bb     = (const float*)d_in[6];
    const int* src_un   = (const int*)d_in[7];
    const int* dst_un   = (const int*)d_in[8];
    const int* src_nu   = (const int*)d_in[9];
    const int* dst_nu   = (const int*)d_in[10];

    int NU = in_sizes[0] / D;
    int NN = in_sizes[1] / D;
    int E1 = in_sizes[7];
    int E2 = in_sizes[9];

    float* base = nullptr;
    int* deg = nullptr;
    int* idx = nullptr;
    cudaGetSymbolAddress((void**)&base, g_buf);
    cudaGetSymbolAddress((void**)&deg, g_deg);
    cudaGetSymbolAddress((void**)&idx, g_idx);

    char* Zpn = (char*)(base + 6 * SZF);   // packed fp16 Z (news)
    char* Zpu = (char*)(base + 7 * SZF);   // packed fp16 Z (user)
    auto packP = [&](int i) -> char* { return (char*)(base + (10L + i) * SZF); };

    float* wf = base + 22 * SZF;
    char* WzrN = (char*)(wf);
    char* WzrU = (char*)(wf + 131072);
    char* WcN  = (char*)(wf + 262144);
    char* WcU  = (char*)(wf + 262144 + 32768);
    float* bzr_n = wf + 262144 + 4 * 32768;
    float* bzr_u = bzr_n + 256;
    float* bc_n  = bzr_u + 256;
    float* bc_u  = bc_n + 128;

    int* deg_n = deg;
    int* deg_u = deg + MAXN;
    int* ssrc1 = idx;
    int* ssrc2 = idx + MAXE;
    int* off_n = idx + 2 * MAXE;
    int* off_u = off_n + (MAXN + 8);
    int* cur_n = off_u + (MAXN + 8);
    int* cur_u = cur_n + MAXN;

    float* out_u = (float*)d_out;
    float* out_n = (float*)d_out + (long)NU * D;

    long MbU = (long)NU * 128, MbN = (long)NN * 128;

    // ---- one-time host-object setup (first call precedes capture baseline) --
    static bool init_done = false;
    static cudaStream_t s1;
    static cudaEvent_t evFork, evPackXH, evWzrN, evSortE1, evSortE2, evZrN, evHRu, evJoin;
    if (!init_done) {
        cudaFuncSetAttribute(gemm_mma, cudaFuncAttributeMaxDynamicSharedMemorySize, 98304);
        cudaStreamCreateWithFlags(&s1, cudaStreamNonBlocking);
        cudaEventCreateWithFlags(&evFork, cudaEventDisableTiming);
        cudaEventCreateWithFlags(&evPackXH, cudaEventDisableTiming);
        cudaEventCreateWithFlags(&evWzrN, cudaEventDisableTiming);
        cudaEventCreateWithFlags(&evSortE1, cudaEventDisableTiming);
        cudaEventCreateWithFlags(&evSortE2, cudaEventDisableTiming);
        cudaEventCreateWithFlags(&evZrN, cudaEventDisableTiming);
        cudaEventCreateWithFlags(&evHRu, cudaEventDisableTiming);
        cudaEventCreateWithFlags(&evJoin, cudaEventDisableTiming);
        init_done = true;
    }

    // ===== capture fork =====
    cudaEventRecord(evFork, 0);
    cudaStreamWaitEvent(s1, evFork, 0);

    // ===== S0: sort E1 =====
    zero_int<<<(MAXN + 255) / 256, 256>>>(deg_n, MAXN);
    count_deg<<<(E1 + 255) / 256, 256>>>(dst_un, E1, deg_n);
    scan_kernel<<<1, 1024>>>(deg_n, NN, off_n, cur_n);
    scatter_kernel<<<(E1 + 255) / 256, 256>>>(src_un, dst_un, E1, cur_n, ssrc1);
    cudaEventRecord(evSortE1, 0);

    // ===== S1: input packs, zrN-critical weights first, then the rest =====
    pack_hi<<<(NU * 32 + 255) / 256, 256, 0, s1>>>(x_user, NU, packP(0));
    pack_hi<<<(NN * 32 + 255) / 256, 256, 0, s1>>>(x_news, NN, packP(1));
    pack_hi<<<(NU * 32 + 255) / 256, 256, 0, s1>>>(h_user, NU, packP(2));
    pack_hi<<<(NN * 32 + 255) / 256, 256, 0, s1>>>(h_news, NN, packP(3));
    cudaEventRecord(evPackXH, s1);
    pack_w_zr<<<512, 256, 0, s1>>>(Wl, Wr, WzrN, 0);
    build_bias<<<1, 128, 0, s1>>>(bb, bzr_n, bzr_u, bc_n, bc_u);
    cudaEventRecord(evWzrN, s1);
    pack_w_zr<<<512, 256, 0, s1>>>(Wl, Wr, WzrU, 1);
    pack_w2<<<128, 256, 0, s1>>>(Wl, Wr, WcN, 4, 0, 0);
    pack_w2<<<128, 256, 0, s1>>>(Wl, Wr, WcN, 5, 0, 2);
    pack_w2<<<128, 256, 0, s1>>>(Wl, Wr, WcU, 4, 1, 0);
    pack_w2<<<128, 256, 0, s1>>>(Wl, Wr, WcU, 5, 1, 2);

    // ===== S0: gather news aggregates, zr news GEMM =====
    cudaStreamWaitEvent(0, evPackXH, 0);
    gather2_p<<<(NN * 32 + 255) / 256, 256>>>(packP(0), packP(2), MbU, off_n, ssrc1, NN,
                                              packP(4), packP(5), MbN);
    cudaStreamWaitEvent(0, evWzrN, 0);
    {
        GP g{};
        g.hi[0] = packP(4); g.hi[1] = packP(1); g.hi[2] = packP(5); g.hi[3] = packP(3);
        g.B = WzrN; g.bias = bzr_n; g.H = h_news; g.outZ = Zpn; g.outHR = packP(10);
        g.Mb = MbN; g.M = NN; g.N = 256; g.nparts = 4; g.mode = 0;
        gemm_mma<<<dim3((NN + 127) / 128, 2), 256, 98304>>>(g);
    }
    cudaEventRecord(evZrN, 0);

    // ===== S1: sort E2, gather user aggregates, zr user GEMM =====
    zero_int<<<(MAXN + 255) / 256, 256, 0, s1>>>(deg_u, MAXN);
    count_deg<<<(E2 + 255) / 256, 256, 0, s1>>>(dst_nu, E2, deg_u);
    scan_kernel<<<1, 1024, 0, s1>>>(deg_u, NU, off_u, cur_u);
    scatter_kernel<<<(E2 + 255) / 256, 256, 0, s1>>>(src_nu, dst_nu, E2, cur_u, ssrc2);
    cudaEventRecord(evSortE2, s1);
    gather2_p<<<(NU * 32 + 255) / 256, 256, 0, s1>>>(packP(1), packP(3), MbN, off_u, ssrc2, NU,
                                                     packP(6), packP(7), MbU);
    {
        GP g{};
        g.hi[0] = packP(6); g.hi[1] = packP(0); g.hi[2] = packP(7); g.hi[3] = packP(2);
        g.B = WzrU; g.bias = bzr_u; g.H = h_user; g.outZ = Zpu; g.outHR = packP(11);
        g.Mb = MbU; g.M = NU; g.N = 256; g.nparts = 4; g.mode = 0;
        gemm_mma<<<dim3((NU + 127) / 128, 2), 256, 98304, s1>>>(g);
    }
    cudaEventRecord(evHRu, s1);

    // ===== S0: gather1 E2 (PHRN -> PACU), chU GEMM -> out_u =====
    cudaStreamWaitEvent(0, evSortE2, 0);
    gather1_p<<<(NU * 32 + 255) / 256, 256>>>(packP(10), MbN, off_u, ssrc2, NU,
                                              packP(9), MbU);
    cudaStreamWaitEvent(0, evHRu, 0);
    {
        GP g{};
        g.hi[0] = packP(6); g.hi[1] = packP(0); g.hi[2] = packP(9); g.hi[3] = packP(11);
        g.B = WcU; g.bias = bc_u; g.H = h_user; g.Zp = Zpu; g.out0 = out_u;
        g.Mb = MbU; g.M = NU; g.N = 128; g.nparts = 4; g.mode = 2;
        gemm_mma<<<dim3((NU + 127) / 128, 1), 256, 98304>>>(g);
    }

    // ===== S1: gather1 E1 (PHRU -> PACN), chN GEMM -> out_n =====
    cudaStreamWaitEvent(s1, evSortE1, 0);
    gather1_p<<<(NN * 32 + 255) / 256, 256, 0, s1>>>(packP(11), MbU, off_n, ssrc1, NN,
                                                     packP(8), MbN);
    cudaStreamWaitEvent(s1, evZrN, 0);
    {
        GP g{};
        g.hi[0] = packP(4); g.hi[1] = packP(1); g.hi[2] = packP(8); g.hi[3] = packP(10);
        g.B = WcN; g.bias = bc_n; g.H = h_news; g.Zp = Zpn; g.out0 = out_n;
        g.Mb = MbN; g.M = NN; g.N = 128; g.nparts = 4; g.mode = 2;
        gemm_mma<<<dim3((NN + 127) / 128, 1), 256, 98304, s1>>>(g);
    }
    cudaEventRecord(evJoin, s1);

    // ===== join =====
    cudaStreamWaitEvent(0, evJoin, 0);
}